// round 13
// baseline (speedup 1.0000x reference)
#include <cuda_runtime.h>

// Quanvolution quantum filter — closed-form Heisenberg evaluation, scalar,
// occupancy-maxed: 256-thread blocks, 8 blocks/SM (2048 thr = 100% of RF at
// 32 regs). Constants as 12 floats (3x LDS.128); pair products computed
// per-thread in FMA (which has headroom) instead of extra L1 wavefronts.

#define BATCH   8192
#define NPATCH  196
#define NTOT    (BATCH * NPATCH)    // 1605632 = 6272 * 256

__global__ __launch_bounds__(256, 8)
void quanv13_kernel(const float* __restrict__ x,
                    const float* __restrict__ params,
                    float* __restrict__ out)
{
    // Ks: [c0,s0,c1,s1 | c2,s2,c3,s3 | P0,P1,P2,P3]
    __shared__ __align__(16) float Ks[12];

    unsigned n = blockIdx.x * 256u + threadIdx.x;    // patch index (exact grid)
    unsigned b = n / 196u;
    unsigned p = n - b * 196u;
    unsigned r = p / 14u;
    unsigned c = p - r * 14u;

    // Input loads issued before the barrier (overlap with thread-0 init).
    const float* img = x + b * 784u + (2u * r) * 28u + 2u * c;
    float2 top = *reinterpret_cast<const float2*>(img);
    float2 bot = *reinterpret_cast<const float2*>(img + 28);

    if (threadIdx.x == 0) {
        float c0, s0, c1, s1, c2, s2, c3, s3;
        __sincosf(params[4], &s0, &c0);
        __sincosf(params[5], &s1, &c1);
        __sincosf(params[6], &s2, &c2);
        __sincosf(params[7], &s3, &c3);
        Ks[0] = c0; Ks[1] = s0; Ks[2]  = c1;        Ks[3]  = s1;
        Ks[4] = c2; Ks[5] = s2; Ks[6]  = c3;        Ks[7]  = s3;
        Ks[8] = params[0]; Ks[9] = params[1];
        Ks[10] = params[2]; Ks[11] = params[3];
    }
    __syncthreads();

    const float4* Kv = reinterpret_cast<const float4*>(Ks);
    float4 KA = Kv[0];   // c0, s0, c1, s1
    float4 KB = Kv[1];   // c2, s2, c3, s3
    float4 KP = Kv[2];   // P0..P3

    // Pair products (8 muls — cheaper than 4 extra L1 wavefronts).
    float c01  = KA.x * KA.z, s01  = KA.y * KA.w;
    float c0s1 = KA.x * KA.w, s0c1 = KA.y * KA.z;
    float c23  = KB.x * KB.z, s23  = KB.y * KB.w;
    float c2s3 = KB.x * KB.w, s2c3 = KB.y * KB.z;

    // Full angles a_v = x_v + params[0][v]; z = cos a, xs = sin a.
    float z0, x0, z1, x1, z2, x2, z3, x3;
    __sincosf(top.x + KP.x, &x0, &z0);
    __sincosf(top.y + KP.y, &x1, &z1);
    __sincosf(bot.x + KP.z, &x2, &z2);
    __sincosf(bot.y + KP.w, &x3, &z3);

    // Shared pair products.
    float zz01 = z0 * z1, zz02 = z0 * z2, zz03 = z0 * z3;
    float zz13 = z1 * z3, zz23 = z2 * z3;
    float xx01 = x0 * x1, xx02 = x0 * x2, xx03 = x0 * x3;
    float xx12 = x1 * x2, xx13 = x1 * x3, xx23 = x2 * x3;
    float zx23 = z2 * x3;

    // E[Z_0] = c1*( c23*(zz01*z3) - c2s3*(xx01*zx23) )
    //        - s1*( c23*(xx12*z3) + s23*x0 )
    float g1 = fmaf(-c2s3, xx01 * zx23, c23 * (zz01 * z3));
    float g2 = fmaf( s23,  x0,          c23 * (xx12 * z3));
    float e0 = fmaf(-KA.w, g2, KA.z * g1);

    // E[Z_1] = c01*(z0*zz23) + s01*xx02
    float e1 = fmaf(s01, xx02, c01 * (z0 * zz23));

    // E[Z_2] = c2*( c01*zz13 - c0s1*(xx12*zz03) - s0c1*(xx01*z2) )
    //        - s2*( s01*xx03 )
    float i2 = c01 * zz13;
    i2 = fmaf(-c0s1, xx12 * zz03, i2);
    i2 = fmaf(-s0c1, xx01 * z2,   i2);
    float e2 = fmaf(-KB.y, s01 * xx03, KB.x * i2);

    // E[Z_3] = c01*( c23*zz02 - s2c3*(z1*xx23) )
    //        + s01*( c23*(xx02*z3) + s23*x1 )
    //        + s0c1*( c2s3*zx23 - s23*(zz01*x2) )
    //        + c0s1*( s2c3*(z0*xx13) - s23*((zz13*z2)*x0) )
    float h1 = fmaf(-s2c3, z1 * xx23,        c23 * zz02);
    float h2 = fmaf( s23,  x1,               c23 * (xx02 * z3));
    float h3 = fmaf(-s23,  zz01 * x2,        c2s3 * zx23);
    float h4 = fmaf(-s23,  (zz13 * z2) * x0, s2c3 * (z0 * xx13));
    float e3 = c01 * h1;
    e3 = fmaf(s01,  h2, e3);
    e3 = fmaf(s0c1, h3, e3);
    e3 = fmaf(c0s1, h4, e3);

    float4 o;
    o.x = e0; o.y = e1; o.z = e2; o.w = e3;
    reinterpret_cast<float4*>(out)[n] = o;
}

extern "C" void kernel_launch(void* const* d_in, const int* in_sizes, int n_in,
                              void* d_out, int out_size)
{
    const float* x      = (const float*)d_in[0];   // (8192,1,28,28) float32
    const float* params = (const float*)d_in[1];   // (2,4) float32
    float* out          = (float*)d_out;           // (8192, 784) float32

    (void)in_sizes; (void)n_in; (void)out_size;

    const int threads = 256;
    const int blocks  = NTOT / threads;            // 6272, exact
    quanv13_kernel<<<blocks, threads>>>(x, params, out);
}

// round 14
// speedup vs baseline: 1.0364x; 1.0364x over previous
#include <cuda_runtime.h>

// Quanvolution quantum filter — closed-form Heisenberg evaluation, scalar,
// occupancy-maxed: 256-thread blocks, 8 blocks/SM (2048 thr = 100% of RF at
// 32 regs). Constants as 12 floats (3x LDS.128); pair products computed
// per-thread in FMA (which has headroom) instead of extra L1 wavefronts.

#define BATCH   8192
#define NPATCH  196
#define NTOT    (BATCH * NPATCH)    // 1605632 = 6272 * 256

__global__ __launch_bounds__(256, 8)
void quanv13_kernel(const float* __restrict__ x,
                    const float* __restrict__ params,
                    float* __restrict__ out)
{
    // Ks: [c0,s0,c1,s1 | c2,s2,c3,s3 | P0,P1,P2,P3]
    __shared__ __align__(16) float Ks[12];

    unsigned n = blockIdx.x * 256u + threadIdx.x;    // patch index (exact grid)
    unsigned b = n / 196u;
    unsigned p = n - b * 196u;
    unsigned r = p / 14u;
    unsigned c = p - r * 14u;

    // Input loads issued before the barrier (overlap with thread-0 init).
    const float* img = x + b * 784u + (2u * r) * 28u + 2u * c;
    float2 top = *reinterpret_cast<const float2*>(img);
    float2 bot = *reinterpret_cast<const float2*>(img + 28);

    if (threadIdx.x == 0) {
        float c0, s0, c1, s1, c2, s2, c3, s3;
        __sincosf(params[4], &s0, &c0);
        __sincosf(params[5], &s1, &c1);
        __sincosf(params[6], &s2, &c2);
        __sincosf(params[7], &s3, &c3);
        Ks[0] = c0; Ks[1] = s0; Ks[2]  = c1;        Ks[3]  = s1;
        Ks[4] = c2; Ks[5] = s2; Ks[6]  = c3;        Ks[7]  = s3;
        Ks[8] = params[0]; Ks[9] = params[1];
        Ks[10] = params[2]; Ks[11] = params[3];
    }
    __syncthreads();

    const float4* Kv = reinterpret_cast<const float4*>(Ks);
    float4 KA = Kv[0];   // c0, s0, c1, s1
    float4 KB = Kv[1];   // c2, s2, c3, s3
    float4 KP = Kv[2];   // P0..P3

    // Pair products (8 muls — cheaper than 4 extra L1 wavefronts).
    float c01  = KA.x * KA.z, s01  = KA.y * KA.w;
    float c0s1 = KA.x * KA.w, s0c1 = KA.y * KA.z;
    float c23  = KB.x * KB.z, s23  = KB.y * KB.w;
    float c2s3 = KB.x * KB.w, s2c3 = KB.y * KB.z;

    // Full angles a_v = x_v + params[0][v]; z = cos a, xs = sin a.
    float z0, x0, z1, x1, z2, x2, z3, x3;
    __sincosf(top.x + KP.x, &x0, &z0);
    __sincosf(top.y + KP.y, &x1, &z1);
    __sincosf(bot.x + KP.z, &x2, &z2);
    __sincosf(bot.y + KP.w, &x3, &z3);

    // Shared pair products.
    float zz01 = z0 * z1, zz02 = z0 * z2, zz03 = z0 * z3;
    float zz13 = z1 * z3, zz23 = z2 * z3;
    float xx01 = x0 * x1, xx02 = x0 * x2, xx03 = x0 * x3;
    float xx12 = x1 * x2, xx13 = x1 * x3, xx23 = x2 * x3;
    float zx23 = z2 * x3;

    // E[Z_0] = c1*( c23*(zz01*z3) - c2s3*(xx01*zx23) )
    //        - s1*( c23*(xx12*z3) + s23*x0 )
    float g1 = fmaf(-c2s3, xx01 * zx23, c23 * (zz01 * z3));
    float g2 = fmaf( s23,  x0,          c23 * (xx12 * z3));
    float e0 = fmaf(-KA.w, g2, KA.z * g1);

    // E[Z_1] = c01*(z0*zz23) + s01*xx02
    float e1 = fmaf(s01, xx02, c01 * (z0 * zz23));

    // E[Z_2] = c2*( c01*zz13 - c0s1*(xx12*zz03) - s0c1*(xx01*z2) )
    //        - s2*( s01*xx03 )
    float i2 = c01 * zz13;
    i2 = fmaf(-c0s1, xx12 * zz03, i2);
    i2 = fmaf(-s0c1, xx01 * z2,   i2);
    float e2 = fmaf(-KB.y, s01 * xx03, KB.x * i2);

    // E[Z_3] = c01*( c23*zz02 - s2c3*(z1*xx23) )
    //        + s01*( c23*(xx02*z3) + s23*x1 )
    //        + s0c1*( c2s3*zx23 - s23*(zz01*x2) )
    //        + c0s1*( s2c3*(z0*xx13) - s23*((zz13*z2)*x0) )
    float h1 = fmaf(-s2c3, z1 * xx23,        c23 * zz02);
    float h2 = fmaf( s23,  x1,               c23 * (xx02 * z3));
    float h3 = fmaf(-s23,  zz01 * x2,        c2s3 * zx23);
    float h4 = fmaf(-s23,  (zz13 * z2) * x0, s2c3 * (z0 * xx13));
    float e3 = c01 * h1;
    e3 = fmaf(s01,  h2, e3);
    e3 = fmaf(s0c1, h3, e3);
    e3 = fmaf(c0s1, h4, e3);

    float4 o;
    o.x = e0; o.y = e1; o.z = e2; o.w = e3;
    reinterpret_cast<float4*>(out)[n] = o;
}

extern "C" void kernel_launch(void* const* d_in, const int* in_sizes, int n_in,
                              void* d_out, int out_size)
{
    const float* x      = (const float*)d_in[0];   // (8192,1,28,28) float32
    const float* params = (const float*)d_in[1];   // (2,4) float32
    float* out          = (float*)d_out;           // (8192, 784) float32

    (void)in_sizes; (void)n_in; (void)out_size;

    const int threads = 256;
    const int blocks  = NTOT / threads;            // 6272, exact
    quanv13_kernel<<<blocks, threads>>>(x, params, out);
}

// round 15
// speedup vs baseline: 1.1875x; 1.1458x over previous
#include <cuda_runtime.h>

// Quanvolution quantum filter — closed-form Heisenberg evaluation, scalar,
// occupancy-maxed: 256-thread blocks, 8 blocks/SM (2048 thr = 100% of RF at
// 32 regs). Constants as 12 floats (3x LDS.128); pair products computed
// per-thread in FMA (which has headroom) instead of extra L1 wavefronts.

#define BATCH   8192
#define NPATCH  196
#define NTOT    (BATCH * NPATCH)    // 1605632 = 6272 * 256

__global__ __launch_bounds__(256, 8)
void quanv13_kernel(const float* __restrict__ x,
                    const float* __restrict__ params,
                    float* __restrict__ out)
{
    // Ks: [c0,s0,c1,s1 | c2,s2,c3,s3 | P0,P1,P2,P3]
    __shared__ __align__(16) float Ks[12];

    unsigned n = blockIdx.x * 256u + threadIdx.x;    // patch index (exact grid)
    unsigned b = n / 196u;
    unsigned p = n - b * 196u;
    unsigned r = p / 14u;
    unsigned c = p - r * 14u;

    // Input loads issued before the barrier (overlap with thread-0 init).
    const float* img = x + b * 784u + (2u * r) * 28u + 2u * c;
    float2 top = *reinterpret_cast<const float2*>(img);
    float2 bot = *reinterpret_cast<const float2*>(img + 28);

    if (threadIdx.x == 0) {
        float c0, s0, c1, s1, c2, s2, c3, s3;
        __sincosf(params[4], &s0, &c0);
        __sincosf(params[5], &s1, &c1);
        __sincosf(params[6], &s2, &c2);
        __sincosf(params[7], &s3, &c3);
        Ks[0] = c0; Ks[1] = s0; Ks[2]  = c1;        Ks[3]  = s1;
        Ks[4] = c2; Ks[5] = s2; Ks[6]  = c3;        Ks[7]  = s3;
        Ks[8] = params[0]; Ks[9] = params[1];
        Ks[10] = params[2]; Ks[11] = params[3];
    }
    __syncthreads();

    const float4* Kv = reinterpret_cast<const float4*>(Ks);
    float4 KA = Kv[0];   // c0, s0, c1, s1
    float4 KB = Kv[1];   // c2, s2, c3, s3
    float4 KP = Kv[2];   // P0..P3

    // Pair products (8 muls — cheaper than 4 extra L1 wavefronts).
    float c01  = KA.x * KA.z, s01  = KA.y * KA.w;
    float c0s1 = KA.x * KA.w, s0c1 = KA.y * KA.z;
    float c23  = KB.x * KB.z, s23  = KB.y * KB.w;
    float c2s3 = KB.x * KB.w, s2c3 = KB.y * KB.z;

    // Full angles a_v = x_v + params[0][v]; z = cos a, xs = sin a.
    float z0, x0, z1, x1, z2, x2, z3, x3;
    __sincosf(top.x + KP.x, &x0, &z0);
    __sincosf(top.y + KP.y, &x1, &z1);
    __sincosf(bot.x + KP.z, &x2, &z2);
    __sincosf(bot.y + KP.w, &x3, &z3);

    // Shared pair products.
    float zz01 = z0 * z1, zz02 = z0 * z2, zz03 = z0 * z3;
    float zz13 = z1 * z3, zz23 = z2 * z3;
    float xx01 = x0 * x1, xx02 = x0 * x2, xx03 = x0 * x3;
    float xx12 = x1 * x2, xx13 = x1 * x3, xx23 = x2 * x3;
    float zx23 = z2 * x3;

    // E[Z_0] = c1*( c23*(zz01*z3) - c2s3*(xx01*zx23) )
    //        - s1*( c23*(xx12*z3) + s23*x0 )
    float g1 = fmaf(-c2s3, xx01 * zx23, c23 * (zz01 * z3));
    float g2 = fmaf( s23,  x0,          c23 * (xx12 * z3));
    float e0 = fmaf(-KA.w, g2, KA.z * g1);

    // E[Z_1] = c01*(z0*zz23) + s01*xx02
    float e1 = fmaf(s01, xx02, c01 * (z0 * zz23));

    // E[Z_2] = c2*( c01*zz13 - c0s1*(xx12*zz03) - s0c1*(xx01*z2) )
    //        - s2*( s01*xx03 )
    float i2 = c01 * zz13;
    i2 = fmaf(-c0s1, xx12 * zz03, i2);
    i2 = fmaf(-s0c1, xx01 * z2,   i2);
    float e2 = fmaf(-KB.y, s01 * xx03, KB.x * i2);

    // E[Z_3] = c01*( c23*zz02 - s2c3*(z1*xx23) )
    //        + s01*( c23*(xx02*z3) + s23*x1 )
    //        + s0c1*( c2s3*zx23 - s23*(zz01*x2) )
    //        + c0s1*( s2c3*(z0*xx13) - s23*((zz13*z2)*x0) )
    float h1 = fmaf(-s2c3, z1 * xx23,        c23 * zz02);
    float h2 = fmaf( s23,  x1,               c23 * (xx02 * z3));
    float h3 = fmaf(-s23,  zz01 * x2,        c2s3 * zx23);
    float h4 = fmaf(-s23,  (zz13 * z2) * x0, s2c3 * (z0 * xx13));
    float e3 = c01 * h1;
    e3 = fmaf(s01,  h2, e3);
    e3 = fmaf(s0c1, h3, e3);
    e3 = fmaf(c0s1, h4, e3);

    float4 o;
    o.x = e0; o.y = e1; o.z = e2; o.w = e3;
    reinterpret_cast<float4*>(out)[n] = o;
}

extern "C" void kernel_launch(void* const* d_in, const int* in_sizes, int n_in,
                              void* d_out, int out_size)
{
    const float* x      = (const float*)d_in[0];   // (8192,1,28,28) float32
    const float* params = (const float*)d_in[1];   // (2,4) float32
    float* out          = (float*)d_out;           // (8192, 784) float32

    (void)in_sizes; (void)n_in; (void)out_size;

    const int threads = 256;
    const int blocks  = NTOT / threads;            // 6272, exact
    quanv13_kernel<<<blocks, threads>>>(x, params, out);
}